// round 1
// baseline (speedup 1.0000x reference)
#include <cuda_runtime.h>
#include <cuda_bf16.h>
#include <cstdint>

// ---------------------------------------------------------------------------
// Generator_causal: 64 sequential steps. Step i:
//   xm = out * M[:,i], xm[:,i]=0
//   h1 = relu([xm, z_i] @ Wi[i]^T + bi[i])
//   h2 = relu(h1 @ Ws1^T + bs1)
//   h3 = relu(h2 @ Ws2^T + bs2)
//   out[:,i] = sigmoid(h3 @ wf[i] + bf[i])
//
// Strategy: fold M into per-step input weights (prep kernel):
//   A_i[k][n] = M[k,i] * Wi[i][n][k]  (k != i, A_i[i][n] = 0)
// z term handled as rank-1 add in epilogue. All GEMMs bf16 mma.sync m16n8k16
// with fp32 accumulation. Each CTA = 128 batch rows; each warp owns 16 rows
// through all three GEMMs (no inter-warp sync needed after the load phase).
// ---------------------------------------------------------------------------

#define XD 64
#define HD 128
#define BB 65536
#define BM 128
#define NTHREADS 256

// smem layout (bytes). All panels are [rows][64 bf16] with 128B rows, SW128.
#define OFF_X    0u        // X tile:  1 panel  [128][64]  (K=64)      16KB
#define OFF_A    16384u    // A_i:     2 N-panels [64][64]             16KB
#define OFF_W1   32768u    // Ws1^T:   2 N-panels [128][64]            32KB
#define OFF_W2   65536u    // Ws2^T:   2 N-panels [128][64]            32KB
#define OFF_H1   98304u    // h1:      2 K-panels [128][64]            32KB
#define OFF_H2   131072u   // h2:      2 K-panels [128][64]            32KB
#define OFF_Z    163840u   // f32[128]
#define OFF_WZ   164352u
#define OFF_BI   164864u
#define OFF_B1   165376u
#define OFF_B2   165888u
#define OFF_WF   166400u
#define SMEM_BYTES 166912u

__device__ __nv_bfloat16 g_A[XD * XD * HD];   // [step][k][n], mask folded in
__device__ __nv_bfloat16 g_W1[HD * HD];       // [k][n] = Ws1[n][k]
__device__ __nv_bfloat16 g_W2[HD * HD];       // [k][n] = Ws2[n][k]

__device__ __forceinline__ unsigned swz(unsigned off) {
    return off ^ ((off >> 3) & 0x70u);
}

__device__ __forceinline__ void ldsm4(unsigned addr, unsigned &r0, unsigned &r1,
                                      unsigned &r2, unsigned &r3) {
    asm volatile("ldmatrix.sync.aligned.m8n8.x4.shared.b16 {%0,%1,%2,%3}, [%4];"
                 : "=r"(r0), "=r"(r1), "=r"(r2), "=r"(r3) : "r"(addr));
}
__device__ __forceinline__ void ldsm4t(unsigned addr, unsigned &r0, unsigned &r1,
                                       unsigned &r2, unsigned &r3) {
    asm volatile("ldmatrix.sync.aligned.m8n8.x4.trans.shared.b16 {%0,%1,%2,%3}, [%4];"
                 : "=r"(r0), "=r"(r1), "=r"(r2), "=r"(r3) : "r"(addr));
}
__device__ __forceinline__ void mma16816(float *c, unsigned a0, unsigned a1,
                                         unsigned a2, unsigned a3,
                                         unsigned b0, unsigned b1) {
    asm volatile(
        "mma.sync.aligned.m16n8k16.row.col.f32.bf16.bf16.f32 "
        "{%0,%1,%2,%3}, {%4,%5,%6,%7}, {%8,%9}, {%0,%1,%2,%3};"
        : "+f"(c[0]), "+f"(c[1]), "+f"(c[2]), "+f"(c[3])
        : "r"(a0), "r"(a1), "r"(a2), "r"(a3), "r"(b0), "r"(b1));
}

// One [16 rows x 128 cols] GEMM slice for this warp.
// A: row-major [128 m][K] bf16 in K-panels of [128][64] (stride 16KB, SW128).
// B: [K][128 n] bf16 in N-panels (stride bPanelStride, SW128).
template <int K16>
__device__ __forceinline__ void run_gemm(float acc[16][4], unsigned sbase,
                                         unsigned aoffBase, unsigned boffBase,
                                         unsigned bPanelStride, int mb, int lane) {
    const unsigned arow   = (unsigned)(mb + (lane & 15));
    const unsigned half16 = (lane & 16) ? 16u : 0u;
    const unsigned klane  = (unsigned)(lane & 15);
#pragma unroll
    for (int kb = 0; kb < K16; kb++) {
        unsigned a0, a1, a2, a3;
        unsigned aaddr = sbase + aoffBase + (unsigned)(kb >> 2) * 16384u +
                         swz(arow * 128u + (unsigned)(kb & 3) * 32u + half16);
        ldsm4(aaddr, a0, a1, a2, a3);
        unsigned brow = (unsigned)kb * 16u + klane;
#pragma unroll
        for (int ntp = 0; ntp < 8; ntp++) {  // pairs of n8 tiles
            unsigned b0, b1, b2, b3;
            unsigned baddr = sbase + boffBase + (unsigned)(ntp >> 2) * bPanelStride +
                             swz(brow * 128u + (unsigned)(ntp & 3) * 32u + half16);
            ldsm4t(baddr, b0, b1, b2, b3);
            mma16816(acc[2 * ntp],     a0, a1, a2, a3, b0, b1);
            mma16816(acc[2 * ntp + 1], a0, a1, a2, a3, b2, b3);
        }
    }
}

__device__ __forceinline__ void zero_acc(float acc[16][4]) {
#pragma unroll
    for (int t = 0; t < 16; t++) {
        acc[t][0] = 0.f; acc[t][1] = 0.f; acc[t][2] = 0.f; acc[t][3] = 0.f;
    }
}

__global__ void __launch_bounds__(NTHREADS, 1)
step_kernel(int i, const float *__restrict__ z, const float *__restrict__ Wi,
            const float *__restrict__ bi, const float *__restrict__ bs1,
            const float *__restrict__ bs2, const float *__restrict__ wf,
            const float *__restrict__ bfp, float *__restrict__ out) {
    extern __shared__ char smem[];
    const int tid  = threadIdx.x;
    const int lane = tid & 31;
    const int warp = tid >> 5;
    const int mb   = warp * 16;          // 8 warps x 16 rows = 128 rows
    const int R0   = blockIdx.x * BM;
    const unsigned sbase = (unsigned)__cvta_generic_to_shared(smem);

    float *sZ  = (float *)(smem + OFF_Z);
    float *sWz = (float *)(smem + OFF_WZ);
    float *sBi = (float *)(smem + OFF_BI);
    float *sB1 = (float *)(smem + OFF_B1);
    float *sB2 = (float *)(smem + OFF_B2);
    float *sWf = (float *)(smem + OFF_WF);

    // ---- load X tile: out rows [R0, R0+128) x 64 cols, fp32 -> bf16, SW128 ----
#pragma unroll 2
    for (int c = tid; c < BM * XD / 4; c += NTHREADS) {  // 2048 float4 chunks
        int row = c >> 4, f4 = c & 15;
        float4 v = *(const float4 *)(out + (size_t)(R0 + row) * XD + f4 * 4);
        __nv_bfloat162 p0 = __floats2bfloat162_rn(v.x, v.y);
        __nv_bfloat162 p1 = __floats2bfloat162_rn(v.z, v.w);
        unsigned off = swz((unsigned)(row * 128 + f4 * 8));
        uint2 u;
        u.x = *(unsigned *)&p0;
        u.y = *(unsigned *)&p1;
        *(uint2 *)(smem + OFF_X + off) = u;
    }
    // ---- load per-step input weights A_i: [64][128] bf16 -> 2 N-panels ----
    {
        const uint4 *gA = (const uint4 *)(g_A + (size_t)i * XD * HD);
#pragma unroll 2
        for (int c = tid; c < 1024; c += NTHREADS) {  // 16B chunks
            int row = c >> 4, nc = c & 15;
            uint4 v = gA[c];
            unsigned off = (unsigned)(nc >> 3) * 8192u +
                           swz((unsigned)(row * 128 + (nc & 7) * 16));
            *(uint4 *)(smem + OFF_A + off) = v;
        }
        const uint4 *gW1 = (const uint4 *)g_W1;
        const uint4 *gW2 = (const uint4 *)g_W2;
#pragma unroll 2
        for (int c = tid; c < 2048; c += NTHREADS) {
            int row = c >> 4, nc = c & 15;
            unsigned off = (unsigned)(nc >> 3) * 16384u +
                           swz((unsigned)(row * 128 + (nc & 7) * 16));
            *(uint4 *)(smem + OFF_W1 + off) = gW1[c];
            *(uint4 *)(smem + OFF_W2 + off) = gW2[c];
        }
    }
    if (tid < HD) {
        if (tid < BM) sZ[tid] = z[(size_t)(R0 + tid) * XD + i];
        sWz[tid] = Wi[((size_t)i * HD + tid) * (XD + 1) + XD];  // z-column of Wi[i]
        sBi[tid] = bi[i * HD + tid];
        sB1[tid] = bs1[tid];
        sB2[tid] = bs2[tid];
        sWf[tid] = wf[i * HD + tid];
    }
    __syncthreads();

    float acc[16][4];

    // ================= GEMM1: h1 = relu(X @ A_i + z*Wz_i + bi_i) =================
    zero_acc(acc);
    run_gemm<4>(acc, sbase, OFF_X, OFF_A, 8192u, mb, lane);
    {
        const int r0 = mb + (lane >> 2), r1 = r0 + 8;
        const float z0 = sZ[r0], z1 = sZ[r1];
#pragma unroll
        for (int nt = 0; nt < 16; nt++) {
            int c0 = nt * 8 + 2 * (lane & 3);
            float wz0 = sWz[c0], wz1 = sWz[c0 + 1];
            float b0 = sBi[c0], b1 = sBi[c0 + 1];
            float v00 = fmaxf(fmaf(z0, wz0, acc[nt][0]) + b0, 0.f);
            float v01 = fmaxf(fmaf(z0, wz1, acc[nt][1]) + b1, 0.f);
            float v10 = fmaxf(fmaf(z1, wz0, acc[nt][2]) + b0, 0.f);
            float v11 = fmaxf(fmaf(z1, wz1, acc[nt][3]) + b1, 0.f);
            unsigned pbase = OFF_H1 + (unsigned)(nt >> 3) * 16384u;
            unsigned coff  = (unsigned)((c0 & 63) * 2);
            __nv_bfloat162 q0 = __floats2bfloat162_rn(v00, v01);
            __nv_bfloat162 q1 = __floats2bfloat162_rn(v10, v11);
            *(__nv_bfloat162 *)(smem + pbase + swz((unsigned)r0 * 128u + coff)) = q0;
            *(__nv_bfloat162 *)(smem + pbase + swz((unsigned)r1 * 128u + coff)) = q1;
        }
    }
    __syncwarp();

    // ================= GEMM2: h2 = relu(h1 @ Ws1^T + bs1) =================
    zero_acc(acc);
    run_gemm<8>(acc, sbase, OFF_H1, OFF_W1, 16384u, mb, lane);
    {
        const int r0 = mb + (lane >> 2), r1 = r0 + 8;
#pragma unroll
        for (int nt = 0; nt < 16; nt++) {
            int c0 = nt * 8 + 2 * (lane & 3);
            float b0 = sB1[c0], b1 = sB1[c0 + 1];
            float v00 = fmaxf(acc[nt][0] + b0, 0.f);
            float v01 = fmaxf(acc[nt][1] + b1, 0.f);
            float v10 = fmaxf(acc[nt][2] + b0, 0.f);
            float v11 = fmaxf(acc[nt][3] + b1, 0.f);
            unsigned pbase = OFF_H2 + (unsigned)(nt >> 3) * 16384u;
            unsigned coff  = (unsigned)((c0 & 63) * 2);
            __nv_bfloat162 q0 = __floats2bfloat162_rn(v00, v01);
            __nv_bfloat162 q1 = __floats2bfloat162_rn(v10, v11);
            *(__nv_bfloat162 *)(smem + pbase + swz((unsigned)r0 * 128u + coff)) = q0;
            *(__nv_bfloat162 *)(smem + pbase + swz((unsigned)r1 * 128u + coff)) = q1;
        }
    }
    __syncwarp();

    // ========== GEMM3 + head: out[:,i] = sigmoid(relu(h2@Ws2^T+bs2) @ wf_i + bf_i) ==========
    zero_acc(acc);
    run_gemm<8>(acc, sbase, OFF_H2, OFF_W2, 16384u, mb, lane);
    {
        const int r0 = mb + (lane >> 2), r1 = r0 + 8;
        float p0 = 0.f, p1 = 0.f;
#pragma unroll
        for (int nt = 0; nt < 16; nt++) {
            int c0 = nt * 8 + 2 * (lane & 3);
            float b0 = sB2[c0], b1 = sB2[c0 + 1];
            float w0 = sWf[c0], w1 = sWf[c0 + 1];
            p0 += fmaxf(acc[nt][0] + b0, 0.f) * w0 + fmaxf(acc[nt][1] + b1, 0.f) * w1;
            p1 += fmaxf(acc[nt][2] + b0, 0.f) * w0 + fmaxf(acc[nt][3] + b1, 0.f) * w1;
        }
        p0 += __shfl_xor_sync(0xffffffffu, p0, 1);
        p0 += __shfl_xor_sync(0xffffffffu, p0, 2);
        p1 += __shfl_xor_sync(0xffffffffu, p1, 1);
        p1 += __shfl_xor_sync(0xffffffffu, p1, 2);
        if ((lane & 3) == 0) {
            float bfi = bfp[i];
            out[(size_t)(R0 + r0) * XD + i] = 1.f / (1.f + __expf(-(p0 + bfi)));
            out[(size_t)(R0 + r1) * XD + i] = 1.f / (1.f + __expf(-(p1 + bfi)));
        }
    }
}

// ---- prep: fold adjacency mask into per-step bf16 input weights ----
__global__ void prep_A_kernel(const float *__restrict__ M, const float *__restrict__ Wi) {
    int idx = blockIdx.x * blockDim.x + threadIdx.x;
    if (idx >= XD * XD * HD) return;
    int i = idx >> 13;          // / (64*128)
    int k = (idx >> 7) & 63;
    int n = idx & 127;
    float v = (k == i) ? 0.f : M[k * XD + i] * Wi[((size_t)i * HD + n) * (XD + 1) + k];
    g_A[idx] = __float2bfloat16(v);
}

// ---- prep: transpose shared weights to [k][n] bf16 ----
__global__ void prep_W_kernel(const float *__restrict__ Ws1, const float *__restrict__ Ws2) {
    int idx = blockIdx.x * blockDim.x + threadIdx.x;
    if (idx >= HD * HD) return;
    int k = idx >> 7, n = idx & 127;
    g_W1[idx] = __float2bfloat16(Ws1[n * HD + k]);
    g_W2[idx] = __float2bfloat16(Ws2[n * HD + k]);
}

extern "C" void kernel_launch(void *const *d_in, const int *in_sizes, int n_in,
                              void *d_out, int out_size) {
    const float *x   = (const float *)d_in[0];
    const float *z   = (const float *)d_in[1];
    const float *M   = (const float *)d_in[2];
    const float *Wi  = (const float *)d_in[3];
    const float *bi  = (const float *)d_in[4];
    const float *Ws1 = (const float *)d_in[5];
    const float *bs1 = (const float *)d_in[6];
    const float *Ws2 = (const float *)d_in[7];
    const float *bs2 = (const float *)d_in[8];
    const float *wf  = (const float *)d_in[9];
    const float *bf  = (const float *)d_in[10];
    float *out = (float *)d_out;

    cudaFuncSetAttribute(step_kernel, cudaFuncAttributeMaxDynamicSharedMemorySize,
                         (int)SMEM_BYTES);

    prep_A_kernel<<<(XD * XD * HD + 255) / 256, 256>>>(M, Wi);
    prep_W_kernel<<<(HD * HD + 255) / 256, 256>>>(Ws1, Ws2);
    // out starts as x; every column is later overwritten, but columns j>i are
    // read as original x values during step i.
    cudaMemcpyAsync(out, x, (size_t)BB * XD * sizeof(float),
                    cudaMemcpyDeviceToDevice);

    for (int i = 0; i < XD; i++) {
        step_kernel<<<BB / BM, NTHREADS, SMEM_BYTES>>>(i, z, Wi, bi, bs1, bs2,
                                                       wf, bf, out);
    }
}

// round 2
// speedup vs baseline: 1.7056x; 1.7056x over previous
#include <cuda_runtime.h>
#include <cuda_bf16.h>
#include <cstdint>

// ---------------------------------------------------------------------------
// Persistent-per-CTA causal generator.
// Observation: step i's update of out[:, i] depends only on the SAME batch
// rows (xm = out * M[:,i] is elementwise per row). So each CTA owns 128 batch
// rows and runs all 64 steps locally with X resident in shared memory.
//
// Per step i:
//   h1 = relu(X @ A_i + z_i * Wz_i + bi_i)      (A_i has M[:,i] mask folded in)
//   h2 = relu(h1 @ Ws1^T + bs1)
//   h3 = relu(h2 @ Ws2^T + bs2)
//   o  = sigmoid(h3 @ wf_i + bf_i);  X[:, i] = o (bf16), out[:, i] = o (fp32)
//
// 512 threads = 16 warps; warp w owns rows [(w&7)*16, +16) and column half
// (w>>3)*64 of every GEMM. bf16 mma.sync m16n8k16, fp32 accum.
// A_{i+1} + per-step vectors prefetched via cp.async double buffers.
// ---------------------------------------------------------------------------

#define XD 64
#define HD 128
#define BB 65536
#define BM 128
#define NT 512

// smem byte offsets. All bf16 panels: rows of 64 bf16 (128B), SW128 swizzled.
#define OFF_X    0u         // X:  [128][64]                     16384
#define OFF_A    16384u     // A_i: 2 bufs x (2 panels [64][64]) 32768
#define OFF_W1   49152u     // Ws1^T: 2 panels [128][64]         32768
#define OFF_W2   81920u     //                                   32768
#define OFF_H1   114688u    // h1: 2 K-panels [128][64]          32768
#define OFF_H2   147456u    //                                   32768
#define OFF_Z    180224u    // zT fp32 [64][132] (padded)        33792
#define OFF_VEC  214016u    // 2 bufs x (Wz[128],bi[128],wf[128])3072
#define OFF_B1   217088u
#define OFF_B2   217600u
#define OFF_BF   218112u
#define OFF_RED  218368u    // fp32[256]
#define SMEM_BYTES 219392u

#define ZSTRIDE 132

__device__ __nv_bfloat16 g_A[XD * XD * HD];   // [step][k][n], mask folded in
__device__ __nv_bfloat16 g_W1[HD * HD];       // [k][n] = Ws1[n][k]
__device__ __nv_bfloat16 g_W2[HD * HD];       // [k][n] = Ws2[n][k]

__device__ __forceinline__ unsigned swz(unsigned off) {
    return off ^ ((off >> 3) & 0x70u);
}
__device__ __forceinline__ void ldsm4(unsigned addr, unsigned &r0, unsigned &r1,
                                      unsigned &r2, unsigned &r3) {
    asm volatile("ldmatrix.sync.aligned.m8n8.x4.shared.b16 {%0,%1,%2,%3}, [%4];"
                 : "=r"(r0), "=r"(r1), "=r"(r2), "=r"(r3) : "r"(addr));
}
__device__ __forceinline__ void ldsm4t(unsigned addr, unsigned &r0, unsigned &r1,
                                       unsigned &r2, unsigned &r3) {
    asm volatile("ldmatrix.sync.aligned.m8n8.x4.trans.shared.b16 {%0,%1,%2,%3}, [%4];"
                 : "=r"(r0), "=r"(r1), "=r"(r2), "=r"(r3) : "r"(addr));
}
__device__ __forceinline__ void mma16816(float *c, unsigned a0, unsigned a1,
                                         unsigned a2, unsigned a3,
                                         unsigned b0, unsigned b1) {
    asm volatile(
        "mma.sync.aligned.m16n8k16.row.col.f32.bf16.bf16.f32 "
        "{%0,%1,%2,%3}, {%4,%5,%6,%7}, {%8,%9}, {%0,%1,%2,%3};"
        : "+f"(c[0]), "+f"(c[1]), "+f"(c[2]), "+f"(c[3])
        : "r"(a0), "r"(a1), "r"(a2), "r"(a3), "r"(b0), "r"(b1));
}
__device__ __forceinline__ void cp16(unsigned saddr, const void *g) {
    asm volatile("cp.async.cg.shared.global [%0], [%1], 16;" ::"r"(saddr), "l"(g));
}
__device__ __forceinline__ void cp4(unsigned saddr, const void *g) {
    asm volatile("cp.async.ca.shared.global [%0], [%1], 4;" ::"r"(saddr), "l"(g));
}

// Warp computes a [16 rows x 64 cols] GEMM slice.
// A: row-major K-panels [128][64] bf16, panel stride 16384B.
// B: one N-panel [K][64] bf16 at boff.
template <int K16>
__device__ __forceinline__ void run_gemm(float acc[8][4], unsigned sbase,
                                         unsigned aoff, unsigned boff,
                                         int mb, int lane) {
    const unsigned arow   = (unsigned)(mb + (lane & 15));
    const unsigned half16 = (lane & 16) ? 16u : 0u;
    const unsigned klane  = (unsigned)(lane & 15);
#pragma unroll
    for (int kb = 0; kb < K16; kb++) {
        unsigned a0, a1, a2, a3;
        unsigned aaddr = sbase + aoff + (unsigned)(kb >> 2) * 16384u +
                         swz(arow * 128u + (unsigned)(kb & 3) * 32u + half16);
        ldsm4(aaddr, a0, a1, a2, a3);
        unsigned brow = (unsigned)kb * 16u + klane;
#pragma unroll
        for (int ntp = 0; ntp < 4; ntp++) {
            unsigned b0, b1, b2, b3;
            unsigned baddr = sbase + boff +
                             swz(brow * 128u + (unsigned)ntp * 32u + half16);
            ldsm4t(baddr, b0, b1, b2, b3);
            mma16816(acc[2 * ntp],     a0, a1, a2, a3, b0, b1);
            mma16816(acc[2 * ntp + 1], a0, a1, a2, a3, b2, b3);
        }
    }
}

__device__ __forceinline__ void zero_acc(float acc[8][4]) {
#pragma unroll
    for (int t = 0; t < 8; t++) {
        acc[t][0] = 0.f; acc[t][1] = 0.f; acc[t][2] = 0.f; acc[t][3] = 0.f;
    }
}

__device__ __forceinline__ void prefetch_step(int j, unsigned sbase, int tid,
                                              const float *Wi, const float *bi,
                                              const float *wf) {
    const int b = j & 1;
    unsigned abase = sbase + OFF_A + (unsigned)b * 16384u;
    const char *gA = (const char *)g_A + (size_t)j * 16384;
#pragma unroll
    for (int c = tid; c < 1024; c += NT) {
        int row = c >> 4, nc = c & 15;
        unsigned off = (unsigned)(nc >> 3) * 8192u +
                       swz((unsigned)(row * 128 + (nc & 7) * 16));
        cp16(abase + off, gA + c * 16);
    }
    unsigned vbase = sbase + OFF_VEC + (unsigned)b * 1536u;
    if (tid < 128) {
        cp4(vbase + tid * 4, Wi + ((size_t)j * HD + tid) * (XD + 1) + XD);
    } else if (tid < 160) {
        int t = tid - 128;
        cp16(vbase + 512 + t * 16, bi + j * HD + t * 4);
    } else if (tid < 192) {
        int t = tid - 160;
        cp16(vbase + 1024 + t * 16, wf + j * HD + t * 4);
    }
}

__global__ void __launch_bounds__(NT, 1)
gen_kernel(const float *__restrict__ x, const float *__restrict__ z,
           const float *__restrict__ Wi, const float *__restrict__ bi,
           const float *__restrict__ bs1, const float *__restrict__ bs2,
           const float *__restrict__ wf, const float *__restrict__ bfp,
           float *__restrict__ out) {
    extern __shared__ char smem[];
    const int tid  = threadIdx.x;
    const int lane = tid & 31;
    const int warp = tid >> 5;
    const int mb   = (warp & 7) * 16;   // row block within CTA
    const int h    = warp >> 3;         // column half (0/1)
    const int R0   = blockIdx.x * BM;
    const unsigned sbase = (unsigned)__cvta_generic_to_shared(smem);

    float *sZT  = (float *)(smem + OFF_Z);
    float *sB1  = (float *)(smem + OFF_B1);
    float *sB2  = (float *)(smem + OFF_B2);
    float *sBF  = (float *)(smem + OFF_BF);
    float *sRed = (float *)(smem + OFF_RED);

    // ---------------- prologue: resident loads ----------------
    // X tile: x rows [R0, R0+128) x 64 cols, fp32 -> bf16 SW128
#pragma unroll
    for (int c = tid; c < BM * XD / 4; c += NT) {
        int row = c >> 4, f4 = c & 15;
        float4 v = *(const float4 *)(x + (size_t)(R0 + row) * XD + f4 * 4);
        __nv_bfloat162 p0 = __floats2bfloat162_rn(v.x, v.y);
        __nv_bfloat162 p1 = __floats2bfloat162_rn(v.z, v.w);
        unsigned off = swz((unsigned)(row * 128 + f4 * 8));
        uint2 u;
        u.x = *(unsigned *)&p0;
        u.y = *(unsigned *)&p1;
        *(uint2 *)(smem + OFF_X + off) = u;
    }
    // zT: [64 cols][128 rows] fp32, padded stride
#pragma unroll
    for (int idx = tid; idx < BM * XD; idx += NT) {
        int row = idx >> 6, c = idx & 63;
        sZT[c * ZSTRIDE + row] = z[(size_t)(R0 + row) * XD + c];
    }
    // shared weights W1/W2: [128][128] bf16 -> 2 N-panels each
    {
        const uint4 *gW1 = (const uint4 *)g_W1;
        const uint4 *gW2 = (const uint4 *)g_W2;
#pragma unroll
        for (int c = tid; c < 2048; c += NT) {
            int row = c >> 4, nc = c & 15;
            unsigned off = (unsigned)(nc >> 3) * 16384u +
                           swz((unsigned)(row * 128 + (nc & 7) * 16));
            *(uint4 *)(smem + OFF_W1 + off) = gW1[c];
            *(uint4 *)(smem + OFF_W2 + off) = gW2[c];
        }
    }
    if (tid < HD) {
        sB1[tid] = bs1[tid];
        sB2[tid] = bs2[tid];
        if (tid < XD) sBF[tid] = bfp[tid];
    }
    // first-step prefetch
    prefetch_step(0, sbase, tid, Wi, bi, wf);
    asm volatile("cp.async.commit_group;" ::: "memory");

    float acc[8][4];
    const int r0 = mb + (lane >> 2), r1 = r0 + 8;

    // ---------------- 64 sequential steps ----------------
    for (int i = 0; i < XD; i++) {
        const int vb = i & 1;
        const float *sWz = (float *)(smem + OFF_VEC + vb * 1536u);
        const float *sBi = sWz + 128;
        const float *sWf = sWz + 256;

        asm volatile("cp.async.wait_group 0;" ::: "memory");
        __syncthreads();   // A_i/vec_i visible; X col i-1 visible

        // ---- GEMM1: h1 = relu(X @ A_i + z_i*Wz + bi) ----
        zero_acc(acc);
        run_gemm<4>(acc, sbase, OFF_X,
                    OFF_A + (unsigned)vb * 16384u + (unsigned)h * 8192u, mb, lane);
        // overlap: prefetch next step's A + vectors
        if (i + 1 < XD) prefetch_step(i + 1, sbase, tid, Wi, bi, wf);
        asm volatile("cp.async.commit_group;" ::: "memory");
        {
            const float z0 = sZT[i * ZSTRIDE + r0];
            const float z1 = sZT[i * ZSTRIDE + r1];
#pragma unroll
            for (int nt = 0; nt < 8; nt++) {
                int cl = nt * 8 + 2 * (lane & 3);       // col within half
                int c0 = h * 64 + cl;                   // global col
                float wz0 = sWz[c0], wz1 = sWz[c0 + 1];
                float b0 = sBi[c0], b1 = sBi[c0 + 1];
                float v00 = fmaxf(fmaf(z0, wz0, acc[nt][0]) + b0, 0.f);
                float v01 = fmaxf(fmaf(z0, wz1, acc[nt][1]) + b1, 0.f);
                float v10 = fmaxf(fmaf(z1, wz0, acc[nt][2]) + b0, 0.f);
                float v11 = fmaxf(fmaf(z1, wz1, acc[nt][3]) + b1, 0.f);
                unsigned pbase = OFF_H1 + (unsigned)h * 16384u;
                unsigned coff  = (unsigned)(cl * 2);
                __nv_bfloat162 q0 = __floats2bfloat162_rn(v00, v01);
                __nv_bfloat162 q1 = __floats2bfloat162_rn(v10, v11);
                *(__nv_bfloat162 *)(smem + pbase + swz((unsigned)r0 * 128u + coff)) = q0;
                *(__nv_bfloat162 *)(smem + pbase + swz((unsigned)r1 * 128u + coff)) = q1;
            }
        }
        __syncthreads();

        // ---- GEMM2: h2 = relu(h1 @ Ws1^T + bs1) ----
        zero_acc(acc);
        run_gemm<8>(acc, sbase, OFF_H1, OFF_W1 + (unsigned)h * 16384u, mb, lane);
        {
#pragma unroll
            for (int nt = 0; nt < 8; nt++) {
                int cl = nt * 8 + 2 * (lane & 3);
                int c0 = h * 64 + cl;
                float b0 = sB1[c0], b1 = sB1[c0 + 1];
                float v00 = fmaxf(acc[nt][0] + b0, 0.f);
                float v01 = fmaxf(acc[nt][1] + b1, 0.f);
                float v10 = fmaxf(acc[nt][2] + b0, 0.f);
                float v11 = fmaxf(acc[nt][3] + b1, 0.f);
                unsigned pbase = OFF_H2 + (unsigned)h * 16384u;
                unsigned coff  = (unsigned)(cl * 2);
                __nv_bfloat162 q0 = __floats2bfloat162_rn(v00, v01);
                __nv_bfloat162 q1 = __floats2bfloat162_rn(v10, v11);
                *(__nv_bfloat162 *)(smem + pbase + swz((unsigned)r0 * 128u + coff)) = q0;
                *(__nv_bfloat162 *)(smem + pbase + swz((unsigned)r1 * 128u + coff)) = q1;
            }
        }
        __syncthreads();

        // ---- GEMM3 + head: partial dot with wf over this half ----
        zero_acc(acc);
        run_gemm<8>(acc, sbase, OFF_H2, OFF_W2 + (unsigned)h * 16384u, mb, lane);
        {
            float p0 = 0.f, p1 = 0.f;
#pragma unroll
            for (int nt = 0; nt < 8; nt++) {
                int c0 = h * 64 + nt * 8 + 2 * (lane & 3);
                float b0 = sB2[c0], b1 = sB2[c0 + 1];
                float w0 = sWf[c0], w1 = sWf[c0 + 1];
                p0 += fmaxf(acc[nt][0] + b0, 0.f) * w0 + fmaxf(acc[nt][1] + b1, 0.f) * w1;
                p1 += fmaxf(acc[nt][2] + b0, 0.f) * w0 + fmaxf(acc[nt][3] + b1, 0.f) * w1;
            }
            p0 += __shfl_xor_sync(0xffffffffu, p0, 1);
            p0 += __shfl_xor_sync(0xffffffffu, p0, 2);
            p1 += __shfl_xor_sync(0xffffffffu, p1, 1);
            p1 += __shfl_xor_sync(0xffffffffu, p1, 2);
            if ((lane & 3) == 0) {
                sRed[h * BM + r0] = p0;
                sRed[h * BM + r1] = p1;
            }
        }
        __syncthreads();

        // combine halves, sigmoid, write X col i (bf16) + out col i (fp32)
        if (tid < BM) {
            float t = sRed[tid] + sRed[BM + tid] + sBF[i];
            float o = 1.f / (1.f + __expf(-t));
            out[(size_t)(R0 + tid) * XD + i] = o;
            *(__nv_bfloat16 *)(smem + OFF_X + swz((unsigned)(tid * 128 + i * 2))) =
                __float2bfloat16(o);
        }
        // top-of-loop __syncthreads() makes the X update visible to all warps
    }
}

// ---- prep: fold adjacency mask into per-step bf16 input weights ----
__global__ void prep_A_kernel(const float *__restrict__ M, const float *__restrict__ Wi) {
    int idx = blockIdx.x * blockDim.x + threadIdx.x;
    if (idx >= XD * XD * HD) return;
    int i = idx >> 13;
    int k = (idx >> 7) & 63;
    int n = idx & 127;
    float v = (k == i) ? 0.f : M[k * XD + i] * Wi[((size_t)i * HD + n) * (XD + 1) + k];
    g_A[idx] = __float2bfloat16(v);
}

// ---- prep: transpose shared weights to [k][n] bf16 ----
__global__ void prep_W_kernel(const float *__restrict__ Ws1, const float *__restrict__ Ws2) {
    int idx = blockIdx.x * blockDim.x + threadIdx.x;
    if (idx >= HD * HD) return;
    int k = idx >> 7, n = idx & 127;
    g_W1[idx] = __float2bfloat16(Ws1[n * HD + k]);
    g_W2[idx] = __float2bfloat16(Ws2[n * HD + k]);
}

extern "C" void kernel_launch(void *const *d_in, const int *in_sizes, int n_in,
                              void *d_out, int out_size) {
    const float *x   = (const float *)d_in[0];
    const float *z   = (const float *)d_in[1];
    const float *M   = (const float *)d_in[2];
    const float *Wi  = (const float *)d_in[3];
    const float *bi  = (const float *)d_in[4];
    const float *Ws1 = (const float *)d_in[5];
    const float *bs1 = (const float *)d_in[6];
    const float *Ws2 = (const float *)d_in[7];
    const float *bs2 = (const float *)d_in[8];
    const float *wf  = (const float *)d_in[9];
    const float *bf  = (const float *)d_in[10];
    float *out = (float *)d_out;

    cudaFuncSetAttribute(gen_kernel, cudaFuncAttributeMaxDynamicSharedMemorySize,
                         (int)SMEM_BYTES);

    prep_A_kernel<<<(XD * XD * HD + 255) / 256, 256>>>(M, Wi);
    prep_W_kernel<<<(HD * HD + 255) / 256, 256>>>(Ws1, Ws2);
    gen_kernel<<<BB / BM, NT, SMEM_BYTES>>>(x, z, Wi, bi, bs1, bs2, wf, bf, out);
}

// round 3
// speedup vs baseline: 1.8324x; 1.0743x over previous
#include <cuda_runtime.h>
#include <cuda_bf16.h>
#include <cstdint>

// ---------------------------------------------------------------------------
// Persistent-per-CTA causal generator, 32x64 warp tiles (smem-BW optimized).
// Each CTA owns 128 batch rows, runs all 64 steps with X resident in smem.
// 256 threads = 8 warps: warp w -> rows [(w&3)*32, +32), col half (w>>2)*64.
// B fragments loaded once per k-step, reused across the 2 A row-tiles.
// ---------------------------------------------------------------------------

#define XD 64
#define HD 128
#define BB 65536
#define BM 128
#define NT 256

// smem byte offsets. bf16 panels: rows of 64 bf16 (128B), SW128 swizzled.
#define OFF_X    0u         // X:  [128][64]                     16384
#define OFF_A    16384u     // A_i: 2 bufs x (2 panels [64][64]) 32768
#define OFF_W1   49152u     // Ws1^T: 2 panels [128][64]         32768
#define OFF_W2   81920u     //                                   32768
#define OFF_H1   114688u    // h1: 2 K-panels [128][64]          32768
#define OFF_H2   147456u    //                                   32768
#define OFF_Z    180224u    // zT fp32 [64][132] (padded)        33792
#define OFF_VEC  214016u    // 2 bufs x (Wz[128],bi[128],wf[128])3072
#define OFF_B1   217088u
#define OFF_B2   217600u
#define OFF_BF   218112u
#define OFF_RED  218368u    // fp32[256]
#define SMEM_BYTES 219392u

#define ZSTRIDE 132

__device__ __nv_bfloat16 g_A[XD * XD * HD];   // [step][k][n], mask folded in
__device__ __nv_bfloat16 g_W1[HD * HD];       // [k][n] = Ws1[n][k]
__device__ __nv_bfloat16 g_W2[HD * HD];       // [k][n] = Ws2[n][k]

__device__ __forceinline__ unsigned swz(unsigned off) {
    return off ^ ((off >> 3) & 0x70u);
}
__device__ __forceinline__ void ldsm4(unsigned addr, unsigned &r0, unsigned &r1,
                                      unsigned &r2, unsigned &r3) {
    asm volatile("ldmatrix.sync.aligned.m8n8.x4.shared.b16 {%0,%1,%2,%3}, [%4];"
                 : "=r"(r0), "=r"(r1), "=r"(r2), "=r"(r3) : "r"(addr));
}
__device__ __forceinline__ void ldsm4t(unsigned addr, unsigned &r0, unsigned &r1,
                                       unsigned &r2, unsigned &r3) {
    asm volatile("ldmatrix.sync.aligned.m8n8.x4.trans.shared.b16 {%0,%1,%2,%3}, [%4];"
                 : "=r"(r0), "=r"(r1), "=r"(r2), "=r"(r3) : "r"(addr));
}
__device__ __forceinline__ void mma16816(float *c, unsigned a0, unsigned a1,
                                         unsigned a2, unsigned a3,
                                         unsigned b0, unsigned b1) {
    asm volatile(
        "mma.sync.aligned.m16n8k16.row.col.f32.bf16.bf16.f32 "
        "{%0,%1,%2,%3}, {%4,%5,%6,%7}, {%8,%9}, {%0,%1,%2,%3};"
        : "+f"(c[0]), "+f"(c[1]), "+f"(c[2]), "+f"(c[3])
        : "r"(a0), "r"(a1), "r"(a2), "r"(a3), "r"(b0), "r"(b1));
}
__device__ __forceinline__ void cp16(unsigned saddr, const void *g) {
    asm volatile("cp.async.cg.shared.global [%0], [%1], 16;" ::"r"(saddr), "l"(g));
}
__device__ __forceinline__ void cp4(unsigned saddr, const void *g) {
    asm volatile("cp.async.ca.shared.global [%0], [%1], 4;" ::"r"(saddr), "l"(g));
}

// Warp computes a [32 rows x 64 cols] GEMM slice.
// A: row-major K-panels [128][64] bf16, panel stride 16384B, rows mb..mb+32.
// B: one N-panel [K][64] bf16 at boff. B frags reused across both A tiles.
// acc index: [mt*8 + 2*ntp + p]
template <int K16>
__device__ __forceinline__ void run_gemm(float acc[16][4], unsigned sbase,
                                         unsigned aoff, unsigned boff,
                                         int mb, int lane) {
    const unsigned half16 = (lane & 16) ? 16u : 0u;
    const unsigned klane  = (unsigned)(lane & 15);
#pragma unroll
    for (int kb = 0; kb < K16; kb++) {
        unsigned brow = (unsigned)kb * 16u + klane;
        unsigned b[16];
#pragma unroll
        for (int ntp = 0; ntp < 4; ntp++) {
            unsigned baddr = sbase + boff +
                             swz(brow * 128u + (unsigned)ntp * 32u + half16);
            ldsm4t(baddr, b[4 * ntp], b[4 * ntp + 1], b[4 * ntp + 2], b[4 * ntp + 3]);
        }
#pragma unroll
        for (int mt = 0; mt < 2; mt++) {
            unsigned arow = (unsigned)(mb + mt * 16 + (lane & 15));
            unsigned a0, a1, a2, a3;
            unsigned aaddr = sbase + aoff + (unsigned)(kb >> 2) * 16384u +
                             swz(arow * 128u + (unsigned)(kb & 3) * 32u + half16);
            ldsm4(aaddr, a0, a1, a2, a3);
#pragma unroll
            for (int ntp = 0; ntp < 4; ntp++) {
                mma16816(acc[mt * 8 + 2 * ntp],     a0, a1, a2, a3,
                         b[4 * ntp], b[4 * ntp + 1]);
                mma16816(acc[mt * 8 + 2 * ntp + 1], a0, a1, a2, a3,
                         b[4 * ntp + 2], b[4 * ntp + 3]);
            }
        }
    }
}

__device__ __forceinline__ void zero_acc(float acc[16][4]) {
#pragma unroll
    for (int t = 0; t < 16; t++) {
        acc[t][0] = 0.f; acc[t][1] = 0.f; acc[t][2] = 0.f; acc[t][3] = 0.f;
    }
}

__device__ __forceinline__ void prefetch_step(int j, unsigned sbase, int tid,
                                              const float *Wi, const float *bi,
                                              const float *wf) {
    const int b = j & 1;
    unsigned abase = sbase + OFF_A + (unsigned)b * 16384u;
    const char *gA = (const char *)g_A + (size_t)j * 16384;
#pragma unroll
    for (int c = tid; c < 1024; c += NT) {
        int row = c >> 4, nc = c & 15;
        unsigned off = (unsigned)(nc >> 3) * 8192u +
                       swz((unsigned)(row * 128 + (nc & 7) * 16));
        cp16(abase + off, gA + c * 16);
    }
    unsigned vbase = sbase + OFF_VEC + (unsigned)b * 1536u;
    if (tid < 128) {
        cp4(vbase + tid * 4, Wi + ((size_t)j * HD + tid) * (XD + 1) + XD);
    } else if (tid < 160) {
        int t = tid - 128;
        cp16(vbase + 512 + t * 16, bi + j * HD + t * 4);
    } else if (tid < 192) {
        int t = tid - 160;
        cp16(vbase + 1024 + t * 16, wf + j * HD + t * 4);
    }
}

__global__ void __launch_bounds__(NT, 1)
gen_kernel(const float *__restrict__ x, const float *__restrict__ z,
           const float *__restrict__ Wi, const float *__restrict__ bi,
           const float *__restrict__ bs1, const float *__restrict__ bs2,
           const float *__restrict__ wf, const float *__restrict__ bfp,
           float *__restrict__ out) {
    extern __shared__ char smem[];
    const int tid  = threadIdx.x;
    const int lane = tid & 31;
    const int warp = tid >> 5;
    const int mb   = (warp & 3) * 32;   // 4 row groups of 32
    const int h    = warp >> 2;         // column half (0/1)
    const int R0   = blockIdx.x * BM;
    const unsigned sbase = (unsigned)__cvta_generic_to_shared(smem);

    float *sZT  = (float *)(smem + OFF_Z);
    float *sB1  = (float *)(smem + OFF_B1);
    float *sB2  = (float *)(smem + OFF_B2);
    float *sBF  = (float *)(smem + OFF_BF);
    float *sRed = (float *)(smem + OFF_RED);

    // ---------------- prologue: resident loads ----------------
#pragma unroll
    for (int c = tid; c < BM * XD / 4; c += NT) {
        int row = c >> 4, f4 = c & 15;
        float4 v = *(const float4 *)(x + (size_t)(R0 + row) * XD + f4 * 4);
        __nv_bfloat162 p0 = __floats2bfloat162_rn(v.x, v.y);
        __nv_bfloat162 p1 = __floats2bfloat162_rn(v.z, v.w);
        unsigned off = swz((unsigned)(row * 128 + f4 * 8));
        uint2 u;
        u.x = *(unsigned *)&p0;
        u.y = *(unsigned *)&p1;
        *(uint2 *)(smem + OFF_X + off) = u;
    }
#pragma unroll
    for (int idx = tid; idx < BM * XD; idx += NT) {
        int row = idx >> 6, c = idx & 63;
        sZT[c * ZSTRIDE + row] = z[(size_t)(R0 + row) * XD + c];
    }
    {
        const uint4 *gW1 = (const uint4 *)g_W1;
        const uint4 *gW2 = (const uint4 *)g_W2;
#pragma unroll
        for (int c = tid; c < 2048; c += NT) {
            int row = c >> 4, nc = c & 15;
            unsigned off = (unsigned)(nc >> 3) * 16384u +
                           swz((unsigned)(row * 128 + (nc & 7) * 16));
            *(uint4 *)(smem + OFF_W1 + off) = gW1[c];
            *(uint4 *)(smem + OFF_W2 + off) = gW2[c];
        }
    }
    if (tid < HD) {
        sB1[tid] = bs1[tid];
        sB2[tid] = bs2[tid];
        if (tid < XD) sBF[tid] = bfp[tid];
    }
    prefetch_step(0, sbase, tid, Wi, bi, wf);
    asm volatile("cp.async.commit_group;" ::: "memory");

    float acc[16][4];

    // ---------------- 64 sequential steps ----------------
    for (int i = 0; i < XD; i++) {
        const int vb = i & 1;
        const float *sWz = (float *)(smem + OFF_VEC + vb * 1536u);
        const float *sBi = sWz + 128;
        const float *sWf = sWz + 256;

        asm volatile("cp.async.wait_group 0;" ::: "memory");
        __syncthreads();   // A_i/vec_i visible; X col i-1 visible

        // ---- GEMM1: h1 = relu(X @ A_i + z_i*Wz + bi) ----
        zero_acc(acc);
        run_gemm<4>(acc, sbase, OFF_X,
                    OFF_A + (unsigned)vb * 16384u + (unsigned)h * 8192u, mb, lane);
        if (i + 1 < XD) prefetch_step(i + 1, sbase, tid, Wi, bi, wf);
        asm volatile("cp.async.commit_group;" ::: "memory");
#pragma unroll
        for (int mt = 0; mt < 2; mt++) {
            const int r0 = mb + mt * 16 + (lane >> 2), r1 = r0 + 8;
            const float z0 = sZT[i * ZSTRIDE + r0];
            const float z1 = sZT[i * ZSTRIDE + r1];
#pragma unroll
            for (int nt = 0; nt < 8; nt++) {
                float *a = acc[mt * 8 + nt];
                int cl = nt * 8 + 2 * (lane & 3);
                int c0 = h * 64 + cl;
                float wz0 = sWz[c0], wz1 = sWz[c0 + 1];
                float b0 = sBi[c0], b1 = sBi[c0 + 1];
                float v00 = fmaxf(fmaf(z0, wz0, a[0]) + b0, 0.f);
                float v01 = fmaxf(fmaf(z0, wz1, a[1]) + b1, 0.f);
                float v10 = fmaxf(fmaf(z1, wz0, a[2]) + b0, 0.f);
                float v11 = fmaxf(fmaf(z1, wz1, a[3]) + b1, 0.f);
                unsigned pbase = OFF_H1 + (unsigned)h * 16384u;
                unsigned coff  = (unsigned)(cl * 2);
                __nv_bfloat162 q0 = __floats2bfloat162_rn(v00, v01);
                __nv_bfloat162 q1 = __floats2bfloat162_rn(v10, v11);
                *(__nv_bfloat162 *)(smem + pbase + swz((unsigned)r0 * 128u + coff)) = q0;
                *(__nv_bfloat162 *)(smem + pbase + swz((unsigned)r1 * 128u + coff)) = q1;
            }
        }
        __syncthreads();

        // ---- GEMM2: h2 = relu(h1 @ Ws1^T + bs1) ----
        zero_acc(acc);
        run_gemm<8>(acc, sbase, OFF_H1, OFF_W1 + (unsigned)h * 16384u, mb, lane);
#pragma unroll
        for (int mt = 0; mt < 2; mt++) {
            const int r0 = mb + mt * 16 + (lane >> 2), r1 = r0 + 8;
#pragma unroll
            for (int nt = 0; nt < 8; nt++) {
                float *a = acc[mt * 8 + nt];
                int cl = nt * 8 + 2 * (lane & 3);
                int c0 = h * 64 + cl;
                float b0 = sB1[c0], b1 = sB1[c0 + 1];
                float v00 = fmaxf(a[0] + b0, 0.f);
                float v01 = fmaxf(a[1] + b1, 0.f);
                float v10 = fmaxf(a[2] + b0, 0.f);
                float v11 = fmaxf(a[3] + b1, 0.f);
                unsigned pbase = OFF_H2 + (unsigned)h * 16384u;
                unsigned coff  = (unsigned)(cl * 2);
                __nv_bfloat162 q0 = __floats2bfloat162_rn(v00, v01);
                __nv_bfloat162 q1 = __floats2bfloat162_rn(v10, v11);
                *(__nv_bfloat162 *)(smem + pbase + swz((unsigned)r0 * 128u + coff)) = q0;
                *(__nv_bfloat162 *)(smem + pbase + swz((unsigned)r1 * 128u + coff)) = q1;
            }
        }
        __syncthreads();

        // ---- GEMM3 + head ----
        zero_acc(acc);
        run_gemm<8>(acc, sbase, OFF_H2, OFF_W2 + (unsigned)h * 16384u, mb, lane);
#pragma unroll
        for (int mt = 0; mt < 2; mt++) {
            const int r0 = mb + mt * 16 + (lane >> 2), r1 = r0 + 8;
            float p0 = 0.f, p1 = 0.f;
#pragma unroll
            for (int nt = 0; nt < 8; nt++) {
                float *a = acc[mt * 8 + nt];
                int c0 = h * 64 + nt * 8 + 2 * (lane & 3);
                float b0 = sB2[c0], b1 = sB2[c0 + 1];
                float w0 = sWf[c0], w1 = sWf[c0 + 1];
                p0 += fmaxf(a[0] + b0, 0.f) * w0 + fmaxf(a[1] + b1, 0.f) * w1;
                p1 += fmaxf(a[2] + b0, 0.f) * w0 + fmaxf(a[3] + b1, 0.f) * w1;
            }
            p0 += __shfl_xor_sync(0xffffffffu, p0, 1);
            p0 += __shfl_xor_sync(0xffffffffu, p0, 2);
            p1 += __shfl_xor_sync(0xffffffffu, p1, 1);
            p1 += __shfl_xor_sync(0xffffffffu, p1, 2);
            if ((lane & 3) == 0) {
                sRed[h * BM + r0] = p0;
                sRed[h * BM + r1] = p1;
            }
        }
        __syncthreads();

        // combine halves, sigmoid, write X col i (bf16) + out col i (fp32)
        if (tid < BM) {
            float t = sRed[tid] + sRed[BM + tid] + sBF[i];
            float o = 1.f / (1.f + __expf(-t));
            out[(size_t)(R0 + tid) * XD + i] = o;
            *(__nv_bfloat16 *)(smem + OFF_X + swz((unsigned)(tid * 128 + i * 2))) =
                __float2bfloat16(o);
        }
    }
}

// ---- prep: fold adjacency mask into per-step bf16 input weights ----
__global__ void prep_A_kernel(const float *__restrict__ M, const float *__restrict__ Wi) {
    int idx = blockIdx.x * blockDim.x + threadIdx.x;
    if (idx >= XD * XD * HD) return;
    int i = idx >> 13;
    int k = (idx >> 7) & 63;
    int n = idx & 127;
    float v = (k == i) ? 0.f : M[k * XD + i] * Wi[((size_t)i * HD + n) * (XD + 1) + k];
    g_A[idx] = __float2bfloat16(v);
}

// ---- prep: transpose shared weights to [k][n] bf16 ----
__global__ void prep_W_kernel(const float *__restrict__ Ws1, const float *__restrict__ Ws2) {
    int idx = blockIdx.x * blockDim.x + threadIdx.x;
    if (idx >= HD * HD) return;
    int k = idx >> 7, n = idx & 127;
    g_W1[idx] = __float2bfloat16(Ws1[n * HD + k]);
    g_W2[idx] = __float2bfloat16(Ws2[n * HD + k]);
}

extern "C" void kernel_launch(void *const *d_in, const int *in_sizes, int n_in,
                              void *d_out, int out_size) {
    const float *x   = (const float *)d_in[0];
    const float *z   = (const float *)d_in[1];
    const float *M   = (const float *)d_in[2];
    const float *Wi  = (const float *)d_in[3];
    const float *bi  = (const float *)d_in[4];
    const float *Ws1 = (const float *)d_in[5];
    const float *bs1 = (const float *)d_in[6];
    const float *Ws2 = (const float *)d_in[7];
    const float *bs2 = (const float *)d_in[8];
    const float *wf  = (const float *)d_in[9];
    const float *bf  = (const float *)d_in[10];
    float *out = (float *)d_out;

    cudaFuncSetAttribute(gen_kernel, cudaFuncAttributeMaxDynamicSharedMemorySize,
                         (int)SMEM_BYTES);

    prep_A_kernel<<<(XD * XD * HD + 255) / 256, 256>>>(M, Wi);
    prep_W_kernel<<<(HD * HD + 255) / 256, 256>>>(Ws1, Ws2);
    gen_kernel<<<BB / BM, NT, SMEM_BYTES>>>(x, z, Wi, bi, bs1, bs2, wf, bf, out);
}